// round 7
// baseline (speedup 1.0000x reference)
#include <cuda_runtime.h>

// Gray-Scott reaction-diffusion residual.
// y-march + float2 in z + x-PAIR per thread (8 outputs/thread/iter).
// Input:  output [50, 2, 100, 100, 100] fp32  (d_in[0])
// Output: f_u (48,96,96,96) then f_v (48,96,96,96), fp32.

#define SLICE_C  1000000      // u->v channel offset (floats)
#define STRIDE_T 2000000      // per-timestep offset (floats)
#define PLANE    10000
#define ROW      100
#define OUTE     96
#define OUTP     (96*96)
#define OUTVOL   (96*96*96)
#define YCHUNK   24

#define LD2(p, off) (*(const float2*)((p) + (off)))

__device__ __forceinline__ float2 lap2(
    float2 c, float2 zl, float2 zr,
    float2 x1a, float2 x1b, float2 x2a, float2 x2b,
    float2 y1a, float2 y1b, float2 y2a, float2 y2b)
{
    const float S0 = -1.0f / 12.0f;
    const float S1 = 4.0f / 3.0f;
    const float SC = -7.5f;
    const float DXv = 100.0f / 48.0f;
    const float INV_DX2 = 1.0f / (DXv * DXv);
    float s1x = zl.y + c.y + x1a.x + x1b.x + y1a.x + y1b.x;
    float s2x = zl.x + zr.x + x2a.x + x2b.x + y2a.x + y2b.x;
    float s1y = c.x + zr.x + x1a.y + x1b.y + y1a.y + y1b.y;
    float s2y = zl.y + zr.y + x2a.y + x2b.y + y2a.y + y2b.y;
    float2 r;
    r.x = (S1 * s1x + S0 * s2x + SC * c.x) * INV_DX2;
    r.y = (S1 * s1y + S0 * s2y + SC * c.y) * INV_DX2;
    return r;
}

__global__ void __launch_bounds__(96, 5) gs_residual_v7(
    const float* __restrict__ in, float* __restrict__ out)
{
    const int zp = threadIdx.x;                    // 0..47 (z pair)
    const int z  = zp * 2;
    const int x  = blockIdx.x * 4 + threadIdx.y * 2;   // thread handles rows x, x+1
    const int yb = blockIdx.y * YCHUNK;
    const int t  = blockIdx.z;

    // p -> center f2 of input row (x+2), plane yb, channel u, time t.
    const float* p  = in + (long long)t * STRIDE_T
                         + (long long)yb * PLANE
                         + (x + 2) * ROW + (z + 2);
    const float* pn = p + STRIDE_T;                // t+1 (center-plane reads only)

    const float INV_DT = 2.0f;
    const float DU = 0.2f, DV = 0.1f, FF = 0.025f, KK = 0.055f;

    // y-queue of centers for the two rows: [plane][row 0/1]
    float2 qu[5][2], qv[5][2];
#pragma unroll
    for (int i = 0; i < 4; i++) {
        qu[i][0] = LD2(p, i * PLANE);
        qu[i][1] = LD2(p, i * PLANE + ROW);
        qv[i][0] = LD2(p, i * PLANE + SLICE_C);
        qv[i][1] = LD2(p, i * PLANE + ROW + SLICE_C);
    }

    float* ou = out + t * OUTVOL + yb * OUTP + x * OUTE + z;
    float* ov = ou + 48 * OUTVOL;

#pragma unroll 1
    for (int yy = 0; yy < YCHUNK; yy++) {
        // ---- channel u loads (12 f2) ----
        float2 qu40 = LD2(p, 4 * PLANE);
        float2 qu41 = LD2(p, 4 * PLANE + ROW);
        float2 uzl0 = LD2(p, 2 * PLANE - 2);
        float2 uzr0 = LD2(p, 2 * PLANE + 2);
        float2 uzl1 = LD2(p, 2 * PLANE + ROW - 2);
        float2 uzr1 = LD2(p, 2 * PLANE + ROW + 2);
        float2 uxa  = LD2(p, 2 * PLANE - 2 * ROW);   // row x
        float2 uxb  = LD2(p, 2 * PLANE - ROW);       // row x+1
        float2 uxc  = LD2(p, 2 * PLANE + 2 * ROW);   // row x+4
        float2 uxd  = LD2(p, 2 * PLANE + 3 * ROW);   // row x+5
        float2 un0  = LD2(pn, 2 * PLANE);
        float2 un1  = LD2(pn, 2 * PLANE + ROW);
        // ---- channel v loads (12 f2) ----
        float2 qv40 = LD2(p, 4 * PLANE + SLICE_C);
        float2 qv41 = LD2(p, 4 * PLANE + ROW + SLICE_C);
        float2 vzl0 = LD2(p, 2 * PLANE - 2 + SLICE_C);
        float2 vzr0 = LD2(p, 2 * PLANE + 2 + SLICE_C);
        float2 vzl1 = LD2(p, 2 * PLANE + ROW - 2 + SLICE_C);
        float2 vzr1 = LD2(p, 2 * PLANE + ROW + 2 + SLICE_C);
        float2 vxa  = LD2(p, 2 * PLANE - 2 * ROW + SLICE_C);
        float2 vxb  = LD2(p, 2 * PLANE - ROW + SLICE_C);
        float2 vxc  = LD2(p, 2 * PLANE + 2 * ROW + SLICE_C);
        float2 vxd  = LD2(p, 2 * PLANE + 3 * ROW + SLICE_C);
        float2 vn0  = LD2(pn, 2 * PLANE + SLICE_C);
        float2 vn1  = LD2(pn, 2 * PLANE + ROW + SLICE_C);

        qu[4][0] = qu40; qu[4][1] = qu41;
        qv[4][0] = qv40; qv[4][1] = qv41;

        // ---- laplacians ----
        // output row x:   x-taps ±1 -> rows x+1 (uxb), x+3 (qu[2][1]); ±2 -> rows x (uxa), x+4 (uxc)
        float2 lapu0 = lap2(qu[2][0], uzl0, uzr0, uxb, qu[2][1], uxa, uxc,
                            qu[1][0], qu[3][0], qu[0][0], qu[4][0]);
        float2 lapv0 = lap2(qv[2][0], vzl0, vzr0, vxb, qv[2][1], vxa, vxc,
                            qv[1][0], qv[3][0], qv[0][0], qv[4][0]);
        // output row x+1: x-taps ±1 -> rows x+2 (qu[2][0]), x+4 (uxc); ±2 -> rows x+1 (uxb), x+5 (uxd)
        float2 lapu1 = lap2(qu[2][1], uzl1, uzr1, qu[2][0], uxc, uxb, uxd,
                            qu[1][1], qu[3][1], qu[0][1], qu[4][1]);
        float2 lapv1 = lap2(qv[2][1], vzl1, vzr1, qv[2][0], vxc, vxb, vxd,
                            qv[1][1], qv[3][1], qv[0][1], qv[4][1]);

        // ---- reaction + time derivative, row x ----
        {
            float2 uc = qu[2][0], vc = qv[2][0];
            float uvv0 = uc.x * vc.x * vc.x;
            float uvv1 = uc.y * vc.y * vc.y;
            float2 fu, fv;
            fu.x = DU * lapu0.x - uvv0 + FF * (1.0f - uc.x) - (un0.x - uc.x) * INV_DT;
            fu.y = DU * lapu0.y - uvv1 + FF * (1.0f - uc.y) - (un0.y - uc.y) * INV_DT;
            fv.x = DV * lapv0.x + uvv0 - (FF + KK) * vc.x - (vn0.x - vc.x) * INV_DT;
            fv.y = DV * lapv0.y + uvv1 - (FF + KK) * vc.y - (vn0.y - vc.y) * INV_DT;
            *(float2*)ou = fu;
            *(float2*)ov = fv;
        }
        // ---- reaction + time derivative, row x+1 ----
        {
            float2 uc = qu[2][1], vc = qv[2][1];
            float uvv0 = uc.x * vc.x * vc.x;
            float uvv1 = uc.y * vc.y * vc.y;
            float2 fu, fv;
            fu.x = DU * lapu1.x - uvv0 + FF * (1.0f - uc.x) - (un1.x - uc.x) * INV_DT;
            fu.y = DU * lapu1.y - uvv1 + FF * (1.0f - uc.y) - (un1.y - uc.y) * INV_DT;
            fv.x = DV * lapv1.x + uvv0 - (FF + KK) * vc.x - (vn1.x - vc.x) * INV_DT;
            fv.y = DV * lapv1.y + uvv1 - (FF + KK) * vc.y - (vn1.y - vc.y) * INV_DT;
            *(float2*)(ou + OUTE) = fu;
            *(float2*)(ov + OUTE) = fv;
        }

        ou += OUTP;
        ov += OUTP;
        p  += PLANE;
        pn += PLANE;

        // shift queues
#pragma unroll
        for (int i = 0; i < 4; i++) {
            qu[i][0] = qu[i + 1][0]; qu[i][1] = qu[i + 1][1];
            qv[i][0] = qv[i + 1][0]; qv[i][1] = qv[i + 1][1];
        }
    }
}

extern "C" void kernel_launch(void* const* d_in, const int* in_sizes, int n_in,
                              void* d_out, int out_size)
{
    const float* in = (const float*)d_in[0];
    float* out = (float*)d_out;
    dim3 grid(24, 4, 48);    // x-tiles (4 x-rows each), y-chunks, t
    dim3 block(48, 2);       // z-pairs, x-pairs
    gs_residual_v7<<<grid, block>>>(in, out);
}